// round 15
// baseline (speedup 1.0000x reference)
#include <cuda_runtime.h>
#include <math.h>

#define Bn 8
#define Cc 128
#define Nn 4096
#define Kk 16
#define Hh 64
#define Pp (Bn*Nn)          // 32768 points total
#define FLT_BIG 3.402823466e+38f

// ---------------- static device scratch (no allocations allowed) ----------------
__device__ float g_qT[Pp*Cc];        // q transposed  [P][C]
__device__ float g_kT[Pp*Cc];        // k transposed  [P][C]
__device__ float g_vT[Pp*Cc];        // v transposed  [P][C]
__device__ float g_fT[Pp*Cc];        // feats transposed [P][C]
__device__ float g_agg[Pp*Cc];       // aggregated features [P][C]
__device__ float g_hid[Pp*2*Cc];     // out-MLP hidden [P][2C]
__device__ float g_t[Pp*Hh*Kk];      // BN pre-activation [P][H][K]  (134MB)
__device__ float g_e[Pp*Cc*Kk];      // geo_emb + bias  [P][C][K]    (268MB)
__device__ float4 g_pts4[Pp];        // packed (x, y, z, |p|^2)
__device__ int   g_idx[Pp*Kk];       // knn indices (GLOBAL point ids)
__device__ double g_bnsum[Hh];
__device__ double g_bnss[Hh];
__device__ float g_bnscale[Hh];
__device__ float g_bnshift[Hh];

// ---------------- kernel 0: packed points + zero BN accumulators ----------------
__global__ void k_sq(const float* __restrict__ pts) {
    int p = blockIdx.x * 256 + threadIdx.x;
    if (p < Hh) { g_bnsum[p] = 0.0; g_bnss[p] = 0.0; }
    if (p >= Pp) return;
    int b = p >> 12, n = p & (Nn - 1);
    const float* pb = pts + b * 3 * Nn;
    float x = pb[n], y = pb[Nn + n], z = pb[2 * Nn + n];
    g_pts4[p] = make_float4(x, y, z, x * x + y * y + z * z);
}

// ---------------- kernel 1: kNN — filtered round-5-exact top-16, float4 loads ----------------
__global__ __launch_bounds__(256) void k_knn(const float* __restrict__ pts) {
    __shared__ float sd[8][32][16];
    __shared__ int   si[8][32][16];
    int w = threadIdx.x >> 5, lane = threadIdx.x & 31;
    int p = blockIdx.x * 8 + w;
    int b = p >> 12;
    const float4* p4 = g_pts4 + (b << 12);
    float4 q4 = g_pts4[p];
    float qx = q4.x, qy = q4.y, qz = q4.z, sqn = q4.w;

    // ---- phase 1: per-lane top-2 ----
    float d0 = FLT_BIG, d1 = FLT_BIG;
    for (int it = 0; it < Nn / 32; it++) {
        int m = it * 32 + lane;
        float4 c4 = p4[m];
        float inner = fmaf(qx, c4.x, fmaf(qy, c4.y, qz * c4.z));
        float d = sqn + c4.w - 2.0f * inner;
        if (d < d1) { if (d < d0) { d1 = d0; d0 = d; } else d1 = d; }
    }
    // tau = 16th smallest value of the 64 candidates
    float tau = FLT_BIG;
    {
        float e0 = d0, e1 = d1;
        for (int r = 0; r < 16; r++) {
            float v; int sel;
            if (e0 <= e1) { v = e0; sel = 0; } else { v = e1; sel = 1; }
            float bv = v; int bl = lane;
#pragma unroll
            for (int off = 16; off; off >>= 1) {
                float vo = __shfl_xor_sync(0xffffffffu, bv, off);
                int lo = __shfl_xor_sync(0xffffffffu, bl, off);
                if (vo < bv || (vo == bv && lo < bl)) { bv = vo; bl = lo; }
            }
            if (lane == bl) { if (sel == 0) e0 = FLT_BIG; else e1 = FLT_BIG; }
            tau = bv;
        }
    }

    // ---- phase 2: filtered round-5 per-lane sorted insertion ----
    float* buf = sd[w][lane];
    int*   ib  = si[w][lane];
    int cnt = 0;
    for (int it = 0; it < Nn / 32; it++) {
        int m = it * 32 + lane;
        float4 c4 = p4[m];
        float inner = fmaf(qx, c4.x, fmaf(qy, c4.y, qz * c4.z));
        float d = sqn + c4.w - 2.0f * inner;
        if (d <= tau) {
            int t = -1;
            if (cnt < 16)           { t = cnt++; buf[t] = d; ib[t] = m; }
            else if (d < buf[15])   { t = 15;    buf[15] = d; ib[15] = m; }
            for (; t > 0 && buf[t] < buf[t - 1]; t--) {
                float tv = buf[t]; buf[t] = buf[t - 1]; buf[t - 1] = tv;
                int   ti = ib[t];  ib[t]  = ib[t - 1];  ib[t - 1]  = ti;
            }
        }
    }
    __syncwarp();

    // ---- merge: 16 rounds, per-lane head pointer, (value, lane) tie-break ----
    int h = 0;
    for (int t = 0; t < 16; t++) {
        float v = (h < cnt) ? buf[h] : FLT_BIG;
        int id   = (h < cnt) ? ib[h]  : 0;
        int src = lane;
#pragma unroll
        for (int off = 16; off; off >>= 1) {
            float vo = __shfl_xor_sync(0xffffffffu, v, off);
            int io = __shfl_xor_sync(0xffffffffu, id, off);
            int so = __shfl_xor_sync(0xffffffffu, src, off);
            if (vo < v || (vo == v && so < src)) { v = vo; id = io; src = so; }
        }
        if (lane == src) h++;
        if (lane == 0) g_idx[p * Kk + t] = id + (b << 12);   // GLOBAL index
        __syncwarp();
    }
}

// ---------------- kernel 2: q/k/v GEMMs (128x128 tile, 8x8), folds feats transpose ----------------
__global__ __launch_bounds__(256) void k_qkv(const float* __restrict__ feats,
    const float* __restrict__ Wq, const float* __restrict__ bq,
    const float* __restrict__ Wk, const float* __restrict__ bk,
    const float* __restrict__ Wv, const float* __restrict__ bv) {
    const float* W; const float* bias; float* out;
    if (blockIdx.z == 0)      { W = Wq; bias = bq; out = g_qT; }
    else if (blockIdx.z == 1) { W = Wk; bias = bk; out = g_kT; }
    else                      { W = Wv; bias = bv; out = g_vT; }
    __shared__ float As[32 * 129];   // k-major: As[cc][nn]
    __shared__ float Ws[128 * 33];   // Ws[o][kk]
    int tid = threadIdx.x;
    int p0 = blockIdx.x * 128;
    int b = p0 >> 12, n0 = p0 & (Nn - 1);
    const float* fb = feats + b * Cc * Nn;
    int tx = tid & 15, ty = tid >> 4;
    float acc[8][8] = {};
    for (int k0 = 0; k0 < Cc; k0 += 32) {
        {   // coalesced load of feats chunk [32 k][128 n]
            int cc = tid >> 3;            // 0..31
            int nn0 = (tid & 7) * 16;     // 0..112
            const float* src = fb + (k0 + cc) * Nn + n0 + nn0;
#pragma unroll
            for (int u = 0; u < 16; u++) As[cc * 129 + nn0 + u] = src[u];
        }
        {
            int r = tid >> 1, kb = (tid & 1) * 16;
            const float* wsrc = W + r * Cc + k0 + kb;
#pragma unroll
            for (int u = 0; u < 16; u++) Ws[r * 33 + kb + u] = wsrc[u];
        }
        __syncthreads();
        if (blockIdx.z == 0) {   // fold feats transpose: g_fT[p][c]
            int r = tid >> 1, kb = (tid & 1) * 16;
            float* dst = g_fT + (long)(p0 + r) * Cc + k0 + kb;
#pragma unroll
            for (int u = 0; u < 16; u++) dst[u] = As[(kb + u) * 129 + r];
        }
#pragma unroll 8
        for (int kk = 0; kk < 32; kk++) {
            float av[8], bvv[8];
#pragma unroll
            for (int i = 0; i < 8; i++) av[i] = As[kk * 129 + ty + 16 * i];   // points
#pragma unroll
            for (int j = 0; j < 8; j++) bvv[j] = Ws[(tx + 16 * j) * 33 + kk]; // outs
#pragma unroll
            for (int i = 0; i < 8; i++)
#pragma unroll
                for (int j = 0; j < 8; j++) acc[i][j] = fmaf(av[i], bvv[j], acc[i][j]);
        }
        __syncthreads();
    }
#pragma unroll
    for (int i = 0; i < 8; i++) {
        int pp = p0 + ty + 16 * i;
#pragma unroll
        for (int j = 0; j < 8; j++) {
            int o = tx + 16 * j;
            out[(long)pp * Cc + o] = acc[i][j] + bias[o];
        }
    }
}

// ---------------- kernel 3: pass1, 512 threads, 8 points/block ----------------
// SMEM floats: s_w[0,8192) s_e[8192,24704) (s_g1 aliases first 8192)
// s_geo[24704,25088) s_sum[25088,25152) s_ss[25152,25216) s_idx[25216,25344)
// Total 25344 floats = 101376 B -> 2 blocks/SM -> 32 warps/SM; regs capped at 64.
__global__ __launch_bounds__(512, 2) void k_pass1(const float* __restrict__ pts,
    const float* __restrict__ geo_W1, const float* __restrict__ geo_b1,
    const float* __restrict__ geo_W2, const float* __restrict__ geo_b2,
    const float* __restrict__ rel_W1, const float* __restrict__ rel_b1) {
    extern __shared__ float sm[];
    float* s_w   = sm;
    float* s_e   = sm + 8192;
    float* s_g1  = s_e;               // alias: dead before s_e is written
    float* s_geo = sm + 24704;
    float* s_sum = sm + 25088;
    float* s_ss  = sm + 25152;
    int*   s_idx = (int*)(sm + 25216);
    int tid = threadIdx.x;
    int p0 = blockIdx.x * 8;
    int b = p0 >> 12; int n0 = p0 & (Nn - 1);

    if (tid < 128) s_idx[tid] = g_idx[p0 * Kk + tid];
    for (int i = tid; i < 8192; i += 512) s_w[i] = geo_W2[i];
    __syncthreads();
    if (tid < 128) {
        int nb = s_idx[tid] & (Nn - 1);   // within-batch for pts
        int pl = tid >> 4;
        const float* pb = pts + b * 3 * Nn;
#pragma unroll
        for (int c = 0; c < 3; c++)
            s_geo[c * 128 + tid] = pb[c * Nn + n0 + pl] - pb[c * Nn + nb];
    }
    __syncthreads();
    // g1 = relu(geo_W1 @ rel_geo + b1)  -> s_g1 (aliasing s_e's first half)
    for (int idx = tid; idx < 8192; idx += 512) {
        int h = idx >> 7, j = idx & 127;
        float v = fmaf(geo_W1[h * 3 + 2], s_geo[256 + j],
                  fmaf(geo_W1[h * 3 + 1], s_geo[128 + j],
                  fmaf(geo_W1[h * 3 + 0], s_geo[j], geo_b1[h])));
        s_g1[idx] = fmaxf(v, 0.f);
    }
    __syncthreads();
    int tx = tid & 15, ty = tid >> 4;   // ty: 0..31
    // geo_emb = geo_W2 @ g1 + b2   (128x128, k=64); 4x8 microtile, rows ty+32i
    {
        float acc[4][8] = {};
        for (int kk = 0; kk < 64; kk++) {
            float a[4];
#pragma unroll
            for (int i = 0; i < 4; i++) a[i] = s_w[(ty + 32 * i) * 64 + kk];
            float4 b0 = *(const float4*)&s_g1[kk * 128 + tx * 4];
            float4 b1 = *(const float4*)&s_g1[kk * 128 + 64 + tx * 4];
            float bb[8] = { b0.x, b0.y, b0.z, b0.w, b1.x, b1.y, b1.z, b1.w };
#pragma unroll
            for (int i = 0; i < 4; i++)
#pragma unroll
                for (int j = 0; j < 8; j++) acc[i][j] = fmaf(a[i], bb[j], acc[i][j]);
        }
        __syncthreads();   // all reads of s_g1 done before overwriting it via s_e
#pragma unroll
        for (int i = 0; i < 4; i++) {
            int c = ty + 32 * i;
            float bc = geo_b2[c];
#pragma unroll
            for (int j = 0; j < 8; j++) {
                int col = (j < 4) ? (tx * 4 + j) : (64 + tx * 4 + (j - 4));
                float v = acc[i][j] + bc;
                s_e[c * 129 + col] = v;
                int pl = col >> 4, kk2 = col & 15;
                g_e[(long)(p0 + pl) * (Cc * Kk) + c * Kk + kk2] = v;   // buffer for pass2
            }
        }
    }
    __syncthreads();
    // rel = q - knn_k + geo_emb (in place)
    {
        int c = tid & 127, jq = tid >> 7;    // jq: 0..3
        for (int jo = 0; jo < 32; jo++) {
            int j = jo * 4 + jq;
            int pl = j >> 4;
            int nb = s_idx[j];                // GLOBAL index into g_kT
            s_e[c * 129 + j] += g_qT[(p0 + pl) * Cc + c] - g_kT[nb * Cc + c];
        }
    }
    __syncthreads();
    for (int i = tid; i < 8192; i += 512) s_w[i] = rel_W1[i];
    __syncthreads();
    // t = rel_W1 @ rel + b1  (64x128, k=128); 2x8 microtile, rows ty+32i
    {
        float acc[2][8] = {};
        for (int cc = 0; cc < 128; cc++) {
            float a[2], bb[8];
#pragma unroll
            for (int i = 0; i < 2; i++) a[i] = s_w[(ty + 32 * i) * 128 + cc];
#pragma unroll
            for (int j = 0; j < 8; j++) bb[j] = s_e[cc * 129 + tx + 16 * j];
#pragma unroll
            for (int i = 0; i < 2; i++)
#pragma unroll
                for (int j = 0; j < 8; j++) acc[i][j] = fmaf(a[i], bb[j], acc[i][j]);
        }
#pragma unroll
        for (int i = 0; i < 2; i++) {
            int h = ty + 32 * i;
            float bh = rel_b1[h];
            float rs = 0.f, rss = 0.f;
#pragma unroll
            for (int j = 0; j < 8; j++) {
                float v = acc[i][j] + bh;     // column j*16+tx -> point p0+j, k=tx
                g_t[(long)(p0 + j) * (Hh * Kk) + h * Kk + tx] = v;
                rs += v; rss += v * v;
            }
#pragma unroll
            for (int off = 8; off; off >>= 1) {
                rs  += __shfl_xor_sync(0xffffffffu, rs, off);
                rss += __shfl_xor_sync(0xffffffffu, rss, off);
            }
            if (tx == 0) { s_sum[h] = rs; s_ss[h] = rss; }
        }
    }
    __syncthreads();
    if (tid < 64) {
        atomicAdd(&g_bnsum[tid], (double)s_sum[tid]);
        atomicAdd(&g_bnss[tid],  (double)s_ss[tid]);
    }
}

// ---------------- kernel 4: BN finalize ----------------
__global__ void k_bnfin(const float* __restrict__ rel_g, const float* __restrict__ rel_beta) {
    int h = threadIdx.x;
    if (h >= Hh) return;
    double cnt = (double)Pp * Kk;
    double m = g_bnsum[h] / cnt;
    double var = g_bnss[h] / cnt - m * m;
    double inv = 1.0 / sqrt(var + 1e-5);
    double sc = (double)rel_g[h] * inv;
    g_bnscale[h] = (float)sc;
    g_bnshift[h] = (float)((double)rel_beta[h] - m * sc);
}

// ---------------- kernel 5: pass2 slim (BN -> logits -> softmax -> aggregate) ----------------
// SMEM floats: GEMM phase s_w[0,8192) s_h2[8192,16384); then s_l[0,16512) aliases both.
// s_idx at [16512,16640). Total 16640 floats = 66560 B -> 3 blocks/SM.
__global__ __launch_bounds__(256, 3) void k_pass2(const float* __restrict__ rel_W2,
                                                  const float* __restrict__ rel_b2) {
    extern __shared__ float sm[];
    float* s_w  = sm;
    float* s_h2 = sm + 8192;
    float* s_l  = sm;
    int*   s_idx = (int*)(sm + 16512);
    int tid = threadIdx.x;
    int p0 = blockIdx.x * 8;

    if (tid < 128) s_idx[tid] = g_idx[p0 * Kk + tid];
    for (int i = tid; i < 8192; i += 256) s_w[i] = rel_W2[i];
    // h2 = relu(BN(t))
    for (int idx = tid; idx < 8192; idx += 256) {
        int h = idx >> 7, j = idx & 127;
        int pl = j >> 4, kki = j & 15;
        float tv = g_t[(long)(p0 + pl) * (Hh * Kk) + h * Kk + kki];
        s_h2[h * 128 + j] = fmaxf(fmaf(g_bnscale[h], tv, g_bnshift[h]), 0.f);
    }
    __syncthreads();
    int tx = tid & 15, ty = tid >> 4;
    // logits = rel_W2 @ h2 + b2   (128x128, k=64); B operand via LDS.128
    {
        float acc[8][8] = {};
        for (int kk = 0; kk < 64; kk++) {
            float a[8];
#pragma unroll
            for (int i = 0; i < 8; i++) a[i] = s_w[(ty + 16 * i) * 64 + kk];
            float4 b0 = *(const float4*)&s_h2[kk * 128 + tx * 4];
            float4 b1 = *(const float4*)&s_h2[kk * 128 + 64 + tx * 4];
            float bb[8] = { b0.x, b0.y, b0.z, b0.w, b1.x, b1.y, b1.z, b1.w };
#pragma unroll
            for (int i = 0; i < 8; i++)
#pragma unroll
                for (int j = 0; j < 8; j++) acc[i][j] = fmaf(a[i], bb[j], acc[i][j]);
        }
        __syncthreads();   // all reads of s_w/s_h2 done before s_l overwrites them
#pragma unroll
        for (int i = 0; i < 8; i++) {
            int c = ty + 16 * i;
            float bc = rel_b2[c];
#pragma unroll
            for (int j = 0; j < 8; j++) {
                int col = (j < 4) ? (tx * 4 + j) : (64 + tx * 4 + (j - 4));
                s_l[c * 129 + col] = acc[i][j] + bc;
            }
        }
    }
    __syncthreads();
    // softmax over K per (c, point): 1024 rows of 16
    for (int r = tid; r < 1024; r += 256) {
        int c = r & 127, pl = r >> 7;
        float* row = s_l + c * 129 + pl * 16;
        float mx = row[0];
#pragma unroll
        for (int k = 1; k < 16; k++) mx = fmaxf(mx, row[k]);
        float ev[16]; float sum = 0.f;
#pragma unroll
        for (int k = 0; k < 16; k++) { ev[k] = __expf(row[k] - mx); sum += ev[k]; }
        float inv = 1.f / sum;
#pragma unroll
        for (int k = 0; k < 16; k++) row[k] = ev[k] * inv;
    }
    __syncthreads();
    // agg = sum_k attn * (v + geo_emb) + feats   (geo_emb streamed from g_e)
    {
        int c = tid & 127, ph = tid >> 7;
        for (int pl = ph; pl < 8; pl += 2) {
            const float* ge = g_e + (long)(p0 + pl) * (Cc * Kk) + c * Kk;
            float acc = 0.f;
#pragma unroll
            for (int k = 0; k < 16; k++) {
                int j = pl * 16 + k;
                int nb = s_idx[j];            // GLOBAL index into g_vT
                acc = fmaf(s_l[c * 129 + j], g_vT[nb * Cc + c] + ge[k], acc);
            }
            g_agg[(p0 + pl) * Cc + c] = acc + g_fT[(p0 + pl) * Cc + c];
        }
    }
}

// ---------------- kernel 6: out MLP layer 1 (relu), 128x128 tile, 8x8 ----------------
__global__ __launch_bounds__(256) void k_mlp1(const float* __restrict__ W, const float* __restrict__ bias) {
    __shared__ float As[128 * 33], Ws[128 * 33];
    int tid = threadIdx.x;
    int p0 = blockIdx.x * 128, o0 = blockIdx.y * 128;
    int tx = tid & 15, ty = tid >> 4;
    float acc[8][8] = {};
    for (int k0 = 0; k0 < Cc; k0 += 32) {
        int r = tid >> 1, kb = (tid & 1) * 16;
        const float* a = g_agg + (p0 + r) * Cc + k0 + kb;
#pragma unroll
        for (int u = 0; u < 16; u++) As[r * 33 + kb + u] = a[u];
        const float* wsrc = W + (o0 + r) * Cc + k0 + kb;
#pragma unroll
        for (int u = 0; u < 16; u++) Ws[r * 33 + kb + u] = wsrc[u];
        __syncthreads();
#pragma unroll 8
        for (int kk = 0; kk < 32; kk++) {
            float av[8], bv[8];
#pragma unroll
            for (int i = 0; i < 8; i++) av[i] = As[(ty + 16 * i) * 33 + kk];   // points
#pragma unroll
            for (int j = 0; j < 8; j++) bv[j] = Ws[(tx + 16 * j) * 33 + kk];   // outs
#pragma unroll
            for (int i = 0; i < 8; i++)
#pragma unroll
                for (int j = 0; j < 8; j++) acc[i][j] = fmaf(av[i], bv[j], acc[i][j]);
        }
        __syncthreads();
    }
#pragma unroll
    for (int i = 0; i < 8; i++) {
        int p = p0 + ty + 16 * i;
#pragma unroll
        for (int j = 0; j < 8; j++) {
            int o = o0 + tx + 16 * j;
            g_hid[p * (2 * Cc) + o] = fmaxf(acc[i][j] + bias[o], 0.f);
        }
    }
}

// ---------------- kernel 7: out MLP layer 2 + residual, 128x128 tile, 8x8 ----------------
__global__ __launch_bounds__(256) void k_mlp2(const float* __restrict__ W, const float* __restrict__ bias,
                                              float* __restrict__ out) {
    __shared__ float As[128 * 33], Ws[128 * 33];
    int tid = threadIdx.x;
    int p0 = blockIdx.x * 128;
    int tx = tid & 15, ty = tid >> 4;
    float acc[8][8] = {};   // i over outs, j over points
    for (int k0 = 0; k0 < 2 * Cc; k0 += 32) {
        int r = tid >> 1, kb = (tid & 1) * 16;
        const float* a = g_hid + (p0 + r) * (2 * Cc) + k0 + kb;
#pragma unroll
        for (int u = 0; u < 16; u++) As[r * 33 + kb + u] = a[u];
        const float* wsrc = W + r * (2 * Cc) + k0 + kb;   // 128 outs total
#pragma unroll
        for (int u = 0; u < 16; u++) Ws[r * 33 + kb + u] = wsrc[u];
        __syncthreads();
#pragma unroll 8
        for (int kk = 0; kk < 32; kk++) {
            float av[8], bv[8];
#pragma unroll
            for (int i = 0; i < 8; i++) av[i] = Ws[(ty + 16 * i) * 33 + kk];   // outs
#pragma unroll
            for (int j = 0; j < 8; j++) bv[j] = As[(tx + 16 * j) * 33 + kk];   // points
#pragma unroll
            for (int i = 0; i < 8; i++)
#pragma unroll
                for (int j = 0; j < 8; j++) acc[i][j] = fmaf(av[i], bv[j], acc[i][j]);
        }
        __syncthreads();
    }
#pragma unroll
    for (int i = 0; i < 8; i++) {
        int o = ty + 16 * i;
        float bo = bias[o];
#pragma unroll
        for (int j = 0; j < 8; j++) {
            int p = p0 + tx + 16 * j;
            int b = p >> 12, n = p & (Nn - 1);
            out[(long)b * Cc * Nn + o * Nn + n] = acc[i][j] + bo + g_agg[p * Cc + o];
        }
    }
}

// ---------------- launch ----------------
#define SMEM_P1 (25344 * 4)
#define SMEM_P2 (16640 * 4)

extern "C" void kernel_launch(void* const* d_in, const int* in_sizes, int n_in,
                              void* d_out, int out_size) {
    const float* pts   = (const float*)d_in[0];
    const float* feats = (const float*)d_in[1];
    const float* Wq = (const float*)d_in[2];  const float* bq = (const float*)d_in[3];
    const float* Wk = (const float*)d_in[4];  const float* bk = (const float*)d_in[5];
    const float* Wv = (const float*)d_in[6];  const float* bv = (const float*)d_in[7];
    const float* gW1 = (const float*)d_in[8]; const float* gb1 = (const float*)d_in[9];
    const float* gW2 = (const float*)d_in[10];const float* gb2 = (const float*)d_in[11];
    const float* rW1 = (const float*)d_in[12];const float* rb1 = (const float*)d_in[13];
    const float* rg  = (const float*)d_in[14];const float* rbe = (const float*)d_in[15];
    const float* rW2 = (const float*)d_in[16];const float* rb2 = (const float*)d_in[17];
    const float* oW1 = (const float*)d_in[18];const float* ob1 = (const float*)d_in[19];
    const float* oW2 = (const float*)d_in[20];const float* ob2 = (const float*)d_in[21];
    float* out = (float*)d_out;

    cudaFuncSetAttribute(k_pass1, cudaFuncAttributeMaxDynamicSharedMemorySize, SMEM_P1);
    cudaFuncSetAttribute(k_pass2, cudaFuncAttributeMaxDynamicSharedMemorySize, SMEM_P2);

    k_sq  <<<Pp / 256, 256>>>(pts);
    k_qkv <<<dim3(Pp / 128, 1, 3), 256>>>(feats, Wq, bq, Wk, bk, Wv, bv);
    k_knn <<<Pp / 8, 256>>>(pts);
    k_pass1<<<Pp / 8, 512, SMEM_P1>>>(pts, gW1, gb1, gW2, gb2, rW1, rb1);
    k_bnfin<<<1, 64>>>(rg, rbe);
    k_pass2<<<Pp / 8, 256, SMEM_P2>>>(rW2, rb2);
    k_mlp1<<<dim3(Pp / 128, 2), 256>>>(oW1, ob1);
    k_mlp2<<<Pp / 128, 256>>>(oW2, ob2, out);
}

// round 16
// speedup vs baseline: 1.0275x; 1.0275x over previous
#include <cuda_runtime.h>
#include <math.h>

#define Bn 8
#define Cc 128
#define Nn 4096
#define Kk 16
#define Hh 64
#define Pp (Bn*Nn)          // 32768 points total
#define FLT_BIG 3.402823466e+38f

// ---------------- static device scratch (no allocations allowed) ----------------
__device__ float g_qT[Pp*Cc];        // q transposed  [P][C]
__device__ float g_kT[Pp*Cc];        // k transposed  [P][C]
__device__ float g_vT[Pp*Cc];        // v transposed  [P][C]
__device__ float g_fT[Pp*Cc];        // feats transposed [P][C]
__device__ float g_agg[Pp*Cc];       // aggregated features [P][C]
__device__ float g_hid[Pp*2*Cc];     // out-MLP hidden [P][2C]
__device__ float g_t[Pp*Hh*Kk];      // BN pre-activation [P][H][K]  (134MB)
__device__ float g_e[Pp*Cc*Kk];      // geo_emb + bias  [P][C][K]    (268MB)
__device__ float4 g_pts4[Pp];        // packed (x, y, z, |p|^2)
__device__ int   g_idx[Pp*Kk];       // knn indices (GLOBAL point ids)
__device__ double g_bnsum[Hh];
__device__ double g_bnss[Hh];
__device__ float g_bnscale[Hh];
__device__ float g_bnshift[Hh];

// ---------------- kernel 0: packed points + zero BN accumulators ----------------
__global__ void k_sq(const float* __restrict__ pts) {
    int p = blockIdx.x * 256 + threadIdx.x;
    if (p < Hh) { g_bnsum[p] = 0.0; g_bnss[p] = 0.0; }
    if (p >= Pp) return;
    int b = p >> 12, n = p & (Nn - 1);
    const float* pb = pts + b * 3 * Nn;
    float x = pb[n], y = pb[Nn + n], z = pb[2 * Nn + n];
    g_pts4[p] = make_float4(x, y, z, x * x + y * y + z * z);
}

// ---------------- kernel 1: kNN — filtered round-5-exact top-16, float4 loads ----------------
__global__ __launch_bounds__(256) void k_knn(const float* __restrict__ pts) {
    __shared__ float sd[8][32][16];
    __shared__ int   si[8][32][16];
    int w = threadIdx.x >> 5, lane = threadIdx.x & 31;
    int p = blockIdx.x * 8 + w;
    int b = p >> 12;
    const float4* p4 = g_pts4 + (b << 12);
    float4 q4 = g_pts4[p];
    float qx = q4.x, qy = q4.y, qz = q4.z, sqn = q4.w;

    // ---- phase 1: per-lane top-2 ----
    float d0 = FLT_BIG, d1 = FLT_BIG;
    for (int it = 0; it < Nn / 32; it++) {
        int m = it * 32 + lane;
        float4 c4 = p4[m];
        float inner = fmaf(qx, c4.x, fmaf(qy, c4.y, qz * c4.z));
        float d = sqn + c4.w - 2.0f * inner;
        if (d < d1) { if (d < d0) { d1 = d0; d0 = d; } else d1 = d; }
    }
    // tau = 16th smallest value of the 64 candidates
    float tau = FLT_BIG;
    {
        float e0 = d0, e1 = d1;
        for (int r = 0; r < 16; r++) {
            float v; int sel;
            if (e0 <= e1) { v = e0; sel = 0; } else { v = e1; sel = 1; }
            float bv = v; int bl = lane;
#pragma unroll
            for (int off = 16; off; off >>= 1) {
                float vo = __shfl_xor_sync(0xffffffffu, bv, off);
                int lo = __shfl_xor_sync(0xffffffffu, bl, off);
                if (vo < bv || (vo == bv && lo < bl)) { bv = vo; bl = lo; }
            }
            if (lane == bl) { if (sel == 0) e0 = FLT_BIG; else e1 = FLT_BIG; }
            tau = bv;
        }
    }

    // ---- phase 2: filtered round-5 per-lane sorted insertion ----
    float* buf = sd[w][lane];
    int*   ib  = si[w][lane];
    int cnt = 0;
    for (int it = 0; it < Nn / 32; it++) {
        int m = it * 32 + lane;
        float4 c4 = p4[m];
        float inner = fmaf(qx, c4.x, fmaf(qy, c4.y, qz * c4.z));
        float d = sqn + c4.w - 2.0f * inner;
        if (d <= tau) {
            int t = -1;
            if (cnt < 16)           { t = cnt++; buf[t] = d; ib[t] = m; }
            else if (d < buf[15])   { t = 15;    buf[15] = d; ib[15] = m; }
            for (; t > 0 && buf[t] < buf[t - 1]; t--) {
                float tv = buf[t]; buf[t] = buf[t - 1]; buf[t - 1] = tv;
                int   ti = ib[t];  ib[t]  = ib[t - 1];  ib[t - 1]  = ti;
            }
        }
    }
    __syncwarp();

    // ---- merge: 16 rounds, per-lane head pointer, (value, lane) tie-break ----
    int h = 0;
    for (int t = 0; t < 16; t++) {
        float v = (h < cnt) ? buf[h] : FLT_BIG;
        int id   = (h < cnt) ? ib[h]  : 0;
        int src = lane;
#pragma unroll
        for (int off = 16; off; off >>= 1) {
            float vo = __shfl_xor_sync(0xffffffffu, v, off);
            int io = __shfl_xor_sync(0xffffffffu, id, off);
            int so = __shfl_xor_sync(0xffffffffu, src, off);
            if (vo < v || (vo == v && so < src)) { v = vo; id = io; src = so; }
        }
        if (lane == src) h++;
        if (lane == 0) g_idx[p * Kk + t] = id + (b << 12);   // GLOBAL index
        __syncwarp();
    }
}

// ---------------- kernel 2: q/k/v GEMMs (128x128 tile, 8x8), folds feats transpose ----------------
__global__ __launch_bounds__(256) void k_qkv(const float* __restrict__ feats,
    const float* __restrict__ Wq, const float* __restrict__ bq,
    const float* __restrict__ Wk, const float* __restrict__ bk,
    const float* __restrict__ Wv, const float* __restrict__ bv) {
    const float* W; const float* bias; float* out;
    if (blockIdx.z == 0)      { W = Wq; bias = bq; out = g_qT; }
    else if (blockIdx.z == 1) { W = Wk; bias = bk; out = g_kT; }
    else                      { W = Wv; bias = bv; out = g_vT; }
    __shared__ float As[32 * 129];   // k-major: As[cc][nn]
    __shared__ float Ws[128 * 33];   // Ws[o][kk]
    int tid = threadIdx.x;
    int p0 = blockIdx.x * 128;
    int b = p0 >> 12, n0 = p0 & (Nn - 1);
    const float* fb = feats + b * Cc * Nn;
    int tx = tid & 15, ty = tid >> 4;
    float acc[8][8] = {};
    for (int k0 = 0; k0 < Cc; k0 += 32) {
        {   // coalesced load of feats chunk [32 k][128 n]
            int cc = tid >> 3;            // 0..31
            int nn0 = (tid & 7) * 16;     // 0..112
            const float* src = fb + (k0 + cc) * Nn + n0 + nn0;
#pragma unroll
            for (int u = 0; u < 16; u++) As[cc * 129 + nn0 + u] = src[u];
        }
        {
            int r = tid >> 1, kb = (tid & 1) * 16;
            const float* wsrc = W + r * Cc + k0 + kb;
#pragma unroll
            for (int u = 0; u < 16; u++) Ws[r * 33 + kb + u] = wsrc[u];
        }
        __syncthreads();
        if (blockIdx.z == 0) {   // fold feats transpose: g_fT[p][c]
            int r = tid >> 1, kb = (tid & 1) * 16;
            float* dst = g_fT + (long)(p0 + r) * Cc + k0 + kb;
#pragma unroll
            for (int u = 0; u < 16; u++) dst[u] = As[(kb + u) * 129 + r];
        }
#pragma unroll 8
        for (int kk = 0; kk < 32; kk++) {
            float av[8], bvv[8];
#pragma unroll
            for (int i = 0; i < 8; i++) av[i] = As[kk * 129 + ty + 16 * i];   // points
#pragma unroll
            for (int j = 0; j < 8; j++) bvv[j] = Ws[(tx + 16 * j) * 33 + kk]; // outs
#pragma unroll
            for (int i = 0; i < 8; i++)
#pragma unroll
                for (int j = 0; j < 8; j++) acc[i][j] = fmaf(av[i], bvv[j], acc[i][j]);
        }
        __syncthreads();
    }
#pragma unroll
    for (int i = 0; i < 8; i++) {
        int pp = p0 + ty + 16 * i;
#pragma unroll
        for (int j = 0; j < 8; j++) {
            int o = tx + 16 * j;
            out[(long)pp * Cc + o] = acc[i][j] + bias[o];
        }
    }
}

// ---------------- kernel 3: pass1, 256 threads, 8 points/block, s_e stride 132 ----------------
// SMEM floats: s_w[0,8192) s_e[8192,25088) stride 132 (s_g1 aliases first 8192)
// s_geo[25088,25472) s_sum[25472,25536) s_ss[25536,25600) s_idx[25600,25728)
// Total 25728 floats = 102912 B -> 2 blocks/SM.
__global__ __launch_bounds__(256, 2) void k_pass1(const float* __restrict__ pts,
    const float* __restrict__ geo_W1, const float* __restrict__ geo_b1,
    const float* __restrict__ geo_W2, const float* __restrict__ geo_b2,
    const float* __restrict__ rel_W1, const float* __restrict__ rel_b1) {
    extern __shared__ float sm[];
    float* s_w   = sm;
    float* s_e   = sm + 8192;          // stride 132
    float* s_g1  = s_e;                // alias: dead before s_e is written
    float* s_geo = sm + 25088;
    float* s_sum = sm + 25472;
    float* s_ss  = sm + 25536;
    int*   s_idx = (int*)(sm + 25600);
    int tid = threadIdx.x;
    int p0 = blockIdx.x * 8;
    int b = p0 >> 12; int n0 = p0 & (Nn - 1);

    if (tid < 128) s_idx[tid] = g_idx[p0 * Kk + tid];
    for (int i = tid; i < 8192; i += 256) s_w[i] = geo_W2[i];
    __syncthreads();
    if (tid < 128) {
        int nb = s_idx[tid] & (Nn - 1);   // within-batch for pts
        int pl = tid >> 4;
        const float* pb = pts + b * 3 * Nn;
#pragma unroll
        for (int c = 0; c < 3; c++)
            s_geo[c * 128 + tid] = pb[c * Nn + n0 + pl] - pb[c * Nn + nb];
    }
    __syncthreads();
    // g1 = relu(geo_W1 @ rel_geo + b1)  -> s_g1 (stride 128, aliasing s_e front)
    for (int idx = tid; idx < 8192; idx += 256) {
        int h = idx >> 7, j = idx & 127;
        float v = fmaf(geo_W1[h * 3 + 2], s_geo[256 + j],
                  fmaf(geo_W1[h * 3 + 1], s_geo[128 + j],
                  fmaf(geo_W1[h * 3 + 0], s_geo[j], geo_b1[h])));
        s_g1[idx] = fmaxf(v, 0.f);
    }
    __syncthreads();
    int tx = tid & 15, ty = tid >> 4;
    // geo_emb = geo_W2 @ g1 + b2   (128x128, k=64); 8x8, B via LDS.128
    // columns: j<4 -> tx*4+j ; j>=4 -> 64 + tx*4 + (j-4)
    {
        float acc[8][8] = {};
        for (int kk = 0; kk < 64; kk++) {
            float a[8];
#pragma unroll
            for (int i = 0; i < 8; i++) a[i] = s_w[(ty + 16 * i) * 64 + kk];
            float4 b0 = *(const float4*)&s_g1[kk * 128 + tx * 4];
            float4 b1 = *(const float4*)&s_g1[kk * 128 + 64 + tx * 4];
            float bb[8] = { b0.x, b0.y, b0.z, b0.w, b1.x, b1.y, b1.z, b1.w };
#pragma unroll
            for (int i = 0; i < 8; i++)
#pragma unroll
                for (int j = 0; j < 8; j++) acc[i][j] = fmaf(a[i], bb[j], acc[i][j]);
        }
        __syncthreads();   // all reads of s_g1 done before overwriting it via s_e
#pragma unroll
        for (int i = 0; i < 8; i++) {
            int c = ty + 16 * i;
            float bc = geo_b2[c];
#pragma unroll
            for (int j = 0; j < 8; j++) {
                int col = (j < 4) ? (tx * 4 + j) : (64 + tx * 4 + (j - 4));
                float v = acc[i][j] + bc;
                s_e[c * 132 + col] = v;
                int pl = col >> 4, kk2 = col & 15;
                g_e[(long)(p0 + pl) * (Cc * Kk) + c * Kk + kk2] = v;   // buffer for pass2
            }
        }
    }
    __syncthreads();
    // rel = q - knn_k + geo_emb (in place)
    {
        int c = tid & 127, jh = tid >> 7;
        for (int jo = 0; jo < 64; jo++) {
            int j = jo * 2 + jh;
            int pl = j >> 4;
            int nb = s_idx[j];                // GLOBAL index into g_kT
            s_e[c * 132 + j] += g_qT[(p0 + pl) * Cc + c] - g_kT[nb * Cc + c];
        }
    }
    __syncthreads();
    for (int i = tid; i < 8192; i += 256) s_w[i] = rel_W1[i];
    __syncthreads();
    // t = rel_W1 @ rel + b1  (64x128, k=128); 4x8, B via LDS.128 (same col remap)
    {
        float acc[4][8] = {};
        for (int cc = 0; cc < 128; cc++) {
            float a[4];
#pragma unroll
            for (int i = 0; i < 4; i++) a[i] = s_w[(ty + 16 * i) * 128 + cc];
            float4 b0 = *(const float4*)&s_e[cc * 132 + tx * 4];
            float4 b1 = *(const float4*)&s_e[cc * 132 + 64 + tx * 4];
            float bb[8] = { b0.x, b0.y, b0.z, b0.w, b1.x, b1.y, b1.z, b1.w };
#pragma unroll
            for (int i = 0; i < 4; i++)
#pragma unroll
                for (int j = 0; j < 8; j++) acc[i][j] = fmaf(a[i], bb[j], acc[i][j]);
        }
#pragma unroll
        for (int i = 0; i < 4; i++) {
            int h = ty + 16 * i;
            float bh = rel_b1[h];
            float rs = 0.f, rss = 0.f;
#pragma unroll
            for (int j = 0; j < 8; j++) {
                int col = (j < 4) ? (tx * 4 + j) : (64 + tx * 4 + (j - 4));
                float v = acc[i][j] + bh;
                int pl = col >> 4, kki = col & 15;
                g_t[(long)(p0 + pl) * (Hh * Kk) + h * Kk + kki] = v;
                rs += v; rss += v * v;
            }
#pragma unroll
            for (int off = 8; off; off >>= 1) {
                rs  += __shfl_xor_sync(0xffffffffu, rs, off);
                rss += __shfl_xor_sync(0xffffffffu, rss, off);
            }
            if (tx == 0) { s_sum[h] = rs; s_ss[h] = rss; }
        }
    }
    __syncthreads();
    if (tid < 64) {
        atomicAdd(&g_bnsum[tid], (double)s_sum[tid]);
        atomicAdd(&g_bnss[tid],  (double)s_ss[tid]);
    }
}

// ---------------- kernel 4: BN finalize ----------------
__global__ void k_bnfin(const float* __restrict__ rel_g, const float* __restrict__ rel_beta) {
    int h = threadIdx.x;
    if (h >= Hh) return;
    double cnt = (double)Pp * Kk;
    double m = g_bnsum[h] / cnt;
    double var = g_bnss[h] / cnt - m * m;
    double inv = 1.0 / sqrt(var + 1e-5);
    double sc = (double)rel_g[h] * inv;
    g_bnscale[h] = (float)sc;
    g_bnshift[h] = (float)((double)rel_beta[h] - m * sc);
}

// ---------------- kernel 5: pass2 slim (BN -> logits -> softmax -> aggregate) ----------------
// SMEM floats: GEMM phase s_w[0,8192) s_h2[8192,16384); then s_l[0,16512) aliases both.
// s_idx at [16512,16640). Total 16640 floats = 66560 B -> 3 blocks/SM.
__global__ __launch_bounds__(256, 3) void k_pass2(const float* __restrict__ rel_W2,
                                                  const float* __restrict__ rel_b2) {
    extern __shared__ float sm[];
    float* s_w  = sm;
    float* s_h2 = sm + 8192;
    float* s_l  = sm;
    int*   s_idx = (int*)(sm + 16512);
    int tid = threadIdx.x;
    int p0 = blockIdx.x * 8;

    if (tid < 128) s_idx[tid] = g_idx[p0 * Kk + tid];
    for (int i = tid; i < 8192; i += 256) s_w[i] = rel_W2[i];
    // h2 = relu(BN(t))
    for (int idx = tid; idx < 8192; idx += 256) {
        int h = idx >> 7, j = idx & 127;
        int pl = j >> 4, kki = j & 15;
        float tv = g_t[(long)(p0 + pl) * (Hh * Kk) + h * Kk + kki];
        s_h2[h * 128 + j] = fmaxf(fmaf(g_bnscale[h], tv, g_bnshift[h]), 0.f);
    }
    __syncthreads();
    int tx = tid & 15, ty = tid >> 4;
    // logits = rel_W2 @ h2 + b2   (128x128, k=64); B operand via LDS.128
    {
        float acc[8][8] = {};
        for (int kk = 0; kk < 64; kk++) {
            float a[8];
#pragma unroll
            for (int i = 0; i < 8; i++) a[i] = s_w[(ty + 16 * i) * 64 + kk];
            float4 b0 = *(const float4*)&s_h2[kk * 128 + tx * 4];
            float4 b1 = *(const float4*)&s_h2[kk * 128 + 64 + tx * 4];
            float bb[8] = { b0.x, b0.y, b0.z, b0.w, b1.x, b1.y, b1.z, b1.w };
#pragma unroll
            for (int i = 0; i < 8; i++)
#pragma unroll
                for (int j = 0; j < 8; j++) acc[i][j] = fmaf(a[i], bb[j], acc[i][j]);
        }
        __syncthreads();   // all reads of s_w/s_h2 done before s_l overwrites them
#pragma unroll
        for (int i = 0; i < 8; i++) {
            int c = ty + 16 * i;
            float bc = rel_b2[c];
#pragma unroll
            for (int j = 0; j < 8; j++) {
                int col = (j < 4) ? (tx * 4 + j) : (64 + tx * 4 + (j - 4));
                s_l[c * 129 + col] = acc[i][j] + bc;
            }
        }
    }
    __syncthreads();
    // softmax over K per (c, point): 1024 rows of 16
    for (int r = tid; r < 1024; r += 256) {
        int c = r & 127, pl = r >> 7;
        float* row = s_l + c * 129 + pl * 16;
        float mx = row[0];
#pragma unroll
        for (int k = 1; k < 16; k++) mx = fmaxf(mx, row[k]);
        float ev[16]; float sum = 0.f;
#pragma unroll
        for (int k = 0; k < 16; k++) { ev[k] = __expf(row[k] - mx); sum += ev[k]; }
        float inv = 1.f / sum;
#pragma unroll
        for (int k = 0; k < 16; k++) row[k] = ev[k] * inv;
    }
    __syncthreads();
    // agg = sum_k attn * (v + geo_emb) + feats   (geo_emb streamed from g_e)
    {
        int c = tid & 127, ph = tid >> 7;
        for (int pl = ph; pl < 8; pl += 2) {
            const float* ge = g_e + (long)(p0 + pl) * (Cc * Kk) + c * Kk;
            float acc = 0.f;
#pragma unroll
            for (int k = 0; k < 16; k++) {
                int j = pl * 16 + k;
                int nb = s_idx[j];            // GLOBAL index into g_vT
                acc = fmaf(s_l[c * 129 + j], g_vT[nb * Cc + c] + ge[k], acc);
            }
            g_agg[(p0 + pl) * Cc + c] = acc + g_fT[(p0 + pl) * Cc + c];
        }
    }
}

// ---------------- kernel 6: out MLP layer 1 (relu), 128x128 tile, 8x8 ----------------
__global__ __launch_bounds__(256) void k_mlp1(const float* __restrict__ W, const float* __restrict__ bias) {
    __shared__ float As[128 * 33], Ws[128 * 33];
    int tid = threadIdx.x;
    int p0 = blockIdx.x * 128, o0 = blockIdx.y * 128;
    int tx = tid & 15, ty = tid >> 4;
    float acc[8][8] = {};
    for (int k0 = 0; k0 < Cc; k0 += 32) {
        int r = tid >> 1, kb = (tid & 1) * 16;
        const float* a = g_agg + (p0 + r) * Cc + k0 + kb;
#pragma unroll
        for (int u = 0; u < 16; u++) As[r * 33 + kb + u] = a[u];
        const float* wsrc = W + (o0 + r) * Cc + k0 + kb;
#pragma unroll
        for (int u = 0; u < 16; u++) Ws[r * 33 + kb + u] = wsrc[u];
        __syncthreads();
#pragma unroll 8
        for (int kk = 0; kk < 32; kk++) {
            float av[8], bv[8];
#pragma unroll
            for (int i = 0; i < 8; i++) av[i] = As[(ty + 16 * i) * 33 + kk];   // points
#pragma unroll
            for (int j = 0; j < 8; j++) bv[j] = Ws[(tx + 16 * j) * 33 + kk];   // outs
#pragma unroll
            for (int i = 0; i < 8; i++)
#pragma unroll
                for (int j = 0; j < 8; j++) acc[i][j] = fmaf(av[i], bv[j], acc[i][j]);
        }
        __syncthreads();
    }
#pragma unroll
    for (int i = 0; i < 8; i++) {
        int p = p0 + ty + 16 * i;
#pragma unroll
        for (int j = 0; j < 8; j++) {
            int o = o0 + tx + 16 * j;
            g_hid[p * (2 * Cc) + o] = fmaxf(acc[i][j] + bias[o], 0.f);
        }
    }
}

// ---------------- kernel 7: out MLP layer 2 + residual, 128x128 tile, 8x8 ----------------
__global__ __launch_bounds__(256) void k_mlp2(const float* __restrict__ W, const float* __restrict__ bias,
                                              float* __restrict__ out) {
    __shared__ float As[128 * 33], Ws[128 * 33];
    int tid = threadIdx.x;
    int p0 = blockIdx.x * 128;
    int tx = tid & 15, ty = tid >> 4;
    float acc[8][8] = {};   // i over outs, j over points
    for (int k0 = 0; k0 < 2 * Cc; k0 += 32) {
        int r = tid >> 1, kb = (tid & 1) * 16;
        const float* a = g_hid + (p0 + r) * (2 * Cc) + k0 + kb;
#pragma unroll
        for (int u = 0; u < 16; u++) As[r * 33 + kb + u] = a[u];
        const float* wsrc = W + r * (2 * Cc) + k0 + kb;   // 128 outs total
#pragma unroll
        for (int u = 0; u < 16; u++) Ws[r * 33 + kb + u] = wsrc[u];
        __syncthreads();
#pragma unroll 8
        for (int kk = 0; kk < 32; kk++) {
            float av[8], bv[8];
#pragma unroll
            for (int i = 0; i < 8; i++) av[i] = Ws[(ty + 16 * i) * 33 + kk];   // outs
#pragma unroll
            for (int j = 0; j < 8; j++) bv[j] = As[(tx + 16 * j) * 33 + kk];   // points
#pragma unroll
            for (int i = 0; i < 8; i++)
#pragma unroll
                for (int j = 0; j < 8; j++) acc[i][j] = fmaf(av[i], bv[j], acc[i][j]);
        }
        __syncthreads();
    }
#pragma unroll
    for (int i = 0; i < 8; i++) {
        int o = ty + 16 * i;
        float bo = bias[o];
#pragma unroll
        for (int j = 0; j < 8; j++) {
            int p = p0 + tx + 16 * j;
            int b = p >> 12, n = p & (Nn - 1);
            out[(long)b * Cc * Nn + o * Nn + n] = acc[i][j] + bo + g_agg[p * Cc + o];
        }
    }
}

// ---------------- launch ----------------
#define SMEM_P1 (25728 * 4)
#define SMEM_P2 (16640 * 4)

extern "C" void kernel_launch(void* const* d_in, const int* in_sizes, int n_in,
                              void* d_out, int out_size) {
    const float* pts   = (const float*)d_in[0];
    const float* feats = (const float*)d_in[1];
    const float* Wq = (const float*)d_in[2];  const float* bq = (const float*)d_in[3];
    const float* Wk = (const float*)d_in[4];  const float* bk = (const float*)d_in[5];
    const float* Wv = (const float*)d_in[6];  const float* bv = (const float*)d_in[7];
    const float* gW1 = (const float*)d_in[8]; const float* gb1 = (const float*)d_in[9];
    const float* gW2 = (const float*)d_in[10];const float* gb2 = (const float*)d_in[11];
    const float* rW1 = (const float*)d_in[12];const float* rb1 = (const float*)d_in[13];
    const float* rg  = (const float*)d_in[14];const float* rbe = (const float*)d_in[15];
    const float* rW2 = (const float*)d_in[16];const float* rb2 = (const float*)d_in[17];
    const float* oW1 = (const float*)d_in[18];const float* ob1 = (const float*)d_in[19];
    const float* oW2 = (const float*)d_in[20];const float* ob2 = (const float*)d_in[21];
    float* out = (float*)d_out;

    cudaFuncSetAttribute(k_pass1, cudaFuncAttributeMaxDynamicSharedMemorySize, SMEM_P1);
    cudaFuncSetAttribute(k_pass2, cudaFuncAttributeMaxDynamicSharedMemorySize, SMEM_P2);

    k_sq  <<<Pp / 256, 256>>>(pts);
    k_qkv <<<dim3(Pp / 128, 1, 3), 256>>>(feats, Wq, bq, Wk, bk, Wv, bv);
    k_knn <<<Pp / 8, 256>>>(pts);
    k_pass1<<<Pp / 8, 256, SMEM_P1>>>(pts, gW1, gb1, gW2, gb2, rW1, rb1);
    k_bnfin<<<1, 64>>>(rg, rbe);
    k_pass2<<<Pp / 8, 256, SMEM_P2>>>(rW2, rb2);
    k_mlp1<<<dim3(Pp / 128, 2), 256>>>(oW1, ob1);
    k_mlp2<<<Pp / 128, 256>>>(oW2, ob2, out);
}